// round 6
// baseline (speedup 1.0000x reference)
#include <cuda_runtime.h>
#include <cuda_bf16.h>

#define T_DIM 512
#define B_DIM 128
#define E_DIM 256
#define KMAX  512
#define TT    16      // t-tile per read block
#define UCAP  192     // staged union window (rows); deeper bands use tail path

// Scratch (__device__ globals: allocation-free).
__device__ float g_Cp[B_DIM * T_DIM];                       // prefix of (d-u), [b][t]
__device__ float g_M [B_DIM * T_DIM];                       // M_t = d_t - Cp_t, [b][t]
__device__ float g_bc[(size_t)T_DIM * B_DIM * KMAX];        // band coeffs [t][b][k]
__device__ int   g_nb[T_DIM * B_DIM];                       // band length [t][b]

__device__ __forceinline__ unsigned long long ffma2(
    unsigned long long a, unsigned long long b, unsigned long long c) {
  unsigned long long d;
  asm("fma.rn.f32x2 %0, %1, %2, %3;" : "=l"(d) : "l"(a), "l"(b), "l"(c));
  return d;
}
__device__ __forceinline__ unsigned long long pack_dup(float c) {
  unsigned long long r; unsigned int cu = __float_as_uint(c);
  asm("mov.b64 %0, {%1, %1};" : "=l"(r) : "r"(cu));
  return r;
}

// ---------------------------------------------------------------------------
// Kernel 1: per-batch inclusive prefix sum of (d - u); emit Cp and M.
// ---------------------------------------------------------------------------
__global__ __launch_bounds__(T_DIM) void prefix_kernel(
    const float* __restrict__ u, const float* __restrict__ d) {
  const int b = blockIdx.x, tid = threadIdx.x;
  __shared__ float s[T_DIM];
  const float dt = d[tid * B_DIM + b];
  s[tid] = dt - u[tid * B_DIM + b];
  __syncthreads();
  #pragma unroll
  for (int off = 1; off < T_DIM; off <<= 1) {
    float o = (tid >= off) ? s[tid - off] : 0.f;
    __syncthreads();
    s[tid] += o;
    __syncthreads();
  }
  const float Cp = s[tid];
  g_Cp[b * T_DIM + tid] = Cp;
  g_M [b * T_DIM + tid] = dt - Cp;
}

// ---------------------------------------------------------------------------
// Kernel 2: coefficient walk, one thread per (t,b). Lanes = consecutive t for
// coalesced M reads. coeff_k = min(Cp_t + runmax M, 1) - prev; stop at 1.
// ---------------------------------------------------------------------------
__global__ __launch_bounds__(256) void walk_kernel() {
  const int b = blockIdx.x >> 1;
  const int t = ((blockIdx.x & 1) << 8) + threadIdx.x;

  const float* __restrict__ Mb = &g_M[b * T_DIM];
  const float Cpt = g_Cp[b * T_DIM + t];
  float* __restrict__ row = &g_bc[((size_t)t * B_DIM + b) * KMAX];

  float rm = -3.4e38f, prev = 0.f;
  int nb = t + 1;
  int k = 0;
  for (int j = t; j >= 0; --j, ++k) {
    rm = fmaxf(rm, __ldg(&Mb[j]));
    const float pc = fminf(Cpt + rm, 1.f);
    row[k] = pc - prev;
    prev = pc;
    if (pc >= 1.f) { nb = k + 1; break; }
  }
  g_nb[t * B_DIM + b] = nb;
}

// ---------------------------------------------------------------------------
// Kernel 3: tiled banded read. Block = (t-tile of TT, b), 64 threads x float4.
// Union of the tile's bands staged as duplicated (c,c) pairs in smem; each v
// row loaded once (LDG.128) and FFMA2'd into TT register accumulators.
// ---------------------------------------------------------------------------
__global__ __launch_bounds__(64) void read_tile_kernel(
    const float* __restrict__ v, float* __restrict__ out) {
  const int t0  = blockIdx.x * TT;
  const int b   = blockIdx.y;
  const int tid = threadIdx.x;
  const int t_hi = t0 + TT - 1;

  __shared__ int    snb[TT];
  __shared__ int    s_jmin;
  __shared__ float2 sc2[TT][UCAP];     // [tl][jj] = (c,c)

  if (tid == 0) s_jmin = 1 << 30;
  __syncthreads();
  if (tid < TT) {
    const int t = t0 + tid;
    const int nb = g_nb[t * B_DIM + b];
    snb[tid] = nb;
    atomicMin(&s_jmin, t - nb + 1);
  }
  __syncthreads();

  const int j_min    = s_jmin;
  const int stage_lo = max(j_min, t_hi - UCAP + 1);
  const int ulen     = t_hi - stage_lo + 1;

  // Stage coefficients (coalesced over k in g_bc).
  #pragma unroll
  for (int tl = 0; tl < TT; ++tl) {
    const int t = t0 + tl;
    const int nb = snb[tl];
    const float* __restrict__ crow = &g_bc[((size_t)t * B_DIM + b) * KMAX];
    for (int jj = tid; jj < ulen; jj += 64) {
      const int k = t - (stage_lo + jj);
      float c = 0.f;
      if (k >= 0 && k < nb) c = crow[k];
      sc2[tl][jj] = make_float2(c, c);
    }
  }
  __syncthreads();

  const ulonglong2* __restrict__ vb =
      (const ulonglong2*)(v + (size_t)b * E_DIM) + tid;   // 16B per thread
  const size_t row2 = (size_t)B_DIM * E_DIM / 4;          // row stride in 16B

  unsigned long long a0[TT], a1[TT];
  #pragma unroll
  for (int tl = 0; tl < TT; ++tl) { a0[tl] = 0ull; a1[tl] = 0ull; }

  // Main staged loop: one v-row load feeds TT outputs.
  for (int jj = 0; jj < ulen; ++jj) {
    const ulonglong2 vv = vb[(size_t)(stage_lo + jj) * row2];
    #pragma unroll
    for (int tl = 0; tl < TT; ++tl) {
      const unsigned long long cc =
          *(const unsigned long long*)&sc2[tl][jj];       // uniform broadcast
      a0[tl] = ffma2(cc, vv.x, a0[tl]);
      a1[tl] = ffma2(cc, vv.y, a1[tl]);
    }
  }

  // Tail: bands deeper than the stage window (rare) — exact path via global.
  for (int j = j_min; j < stage_lo; ++j) {
    const ulonglong2 vv = vb[(size_t)j * row2];
    #pragma unroll
    for (int tl = 0; tl < TT; ++tl) {
      const int t = t0 + tl;
      const int k = t - j;                                // k >= 1 here
      float c = 0.f;
      if (k < snb[tl]) c = __ldg(&g_bc[((size_t)t * B_DIM + b) * KMAX + k]);
      const unsigned long long cc = pack_dup(c);
      a0[tl] = ffma2(cc, vv.x, a0[tl]);
      a1[tl] = ffma2(cc, vv.y, a1[tl]);
    }
  }

  #pragma unroll
  for (int tl = 0; tl < TT; ++tl) {
    ulonglong2 r; r.x = a0[tl]; r.y = a1[tl];
    ((ulonglong2*)out)[((size_t)(t0 + tl) * B_DIM + b) * (E_DIM / 4) + tid] = r;
  }
}

// ---------------------------------------------------------------------------
// Inputs: v [T,B,E] f32, u [T,B] f32, d [T,B] f32. Output: reads [T,B,E] f32.
// ---------------------------------------------------------------------------
extern "C" void kernel_launch(void* const* d_in, const int* in_sizes, int n_in,
                              void* d_out, int out_size) {
  const float* v = (const float*)d_in[0];
  const float* u = (const float*)d_in[1];
  const float* d = (const float*)d_in[2];
  float* out = (float*)d_out;

  prefix_kernel<<<B_DIM, T_DIM>>>(u, d);
  walk_kernel<<<B_DIM * 2, 256>>>();

  dim3 grid(T_DIM / TT, B_DIM);
  read_tile_kernel<<<grid, 64>>>(v, out);
}

// round 9
// speedup vs baseline: 1.3113x; 1.3113x over previous
#include <cuda_runtime.h>
#include <cuda_bf16.h>

#define T_DIM 512
#define B_DIM 128
#define E_DIM 256
#define KMAX  512
#define TT    16     // t-tile per read block
#define CH    64     // j-chunk staged in smem

typedef unsigned long long ull;

// Scratch (__device__ globals: allocation-free).
__device__ float  g_Cp[B_DIM * T_DIM];                 // prefix of (d-u), [b][t]
__device__ float  g_M [B_DIM * T_DIM];                 // M_t = d_t - Cp_t, [b][t]
__device__ float2 g_bc2[(size_t)T_DIM * B_DIM * KMAX]; // band coeffs (c,c) [t][b][k]
__device__ int    g_jmin[(T_DIM / TT) * B_DIM];        // deepest j per (t-tile, b)

__device__ __forceinline__ ull ffma2(ull a, ull b, ull c) {
  ull d;
  asm("fma.rn.f32x2 %0, %1, %2, %3;" : "=l"(d) : "l"(a), "l"(b), "l"(c));
  return d;
}

// ---------------------------------------------------------------------------
// Kernel 1: per-batch inclusive prefix sum of (d - u); emit Cp and M.
// ---------------------------------------------------------------------------
__global__ __launch_bounds__(T_DIM) void prefix_kernel(
    const float* __restrict__ u, const float* __restrict__ d) {
  const int b = blockIdx.x, tid = threadIdx.x;
  __shared__ float s[T_DIM];
  const float dt = d[tid * B_DIM + b];
  s[tid] = dt - u[tid * B_DIM + b];
  __syncthreads();
  #pragma unroll
  for (int off = 1; off < T_DIM; off <<= 1) {
    float o = (tid >= off) ? s[tid - off] : 0.f;
    __syncthreads();
    s[tid] += o;
    __syncthreads();
  }
  const float Cp = s[tid];
  g_Cp[b * T_DIM + tid] = Cp;
  g_M [b * T_DIM + tid] = dt - Cp;
}

// ---------------------------------------------------------------------------
// Kernel 2: coefficient walk, one thread per (t,b); lanes = consecutive t.
//   coeff_k = min(Cp_t + runmax_{j=t-k..t} M_j, 1) - prev;  stop at 1.
// Writes duplicated (c,c) pairs; zero-pads each row up to the 16-t tile's
// deepest j (group min via shfl_xor) so the read kernel needs no guards.
// ---------------------------------------------------------------------------
__global__ __launch_bounds__(256) void walk_kernel() {
  const int b = blockIdx.x >> 1;
  const int t = ((blockIdx.x & 1) << 8) + threadIdx.x;

  const float* __restrict__ Mb = &g_M[b * T_DIM];
  const float Cpt = g_Cp[b * T_DIM + t];
  float2* __restrict__ row = &g_bc2[((size_t)t * B_DIM + b) * KMAX];

  float rm = -3.4e38f, prev = 0.f;
  int nb = t + 1;
  int k = 0;
  for (int j = t; j >= 0; --j, ++k) {
    rm = fmaxf(rm, __ldg(&Mb[j]));
    const float pc = fminf(Cpt + rm, 1.f);
    const float c  = pc - prev;
    row[k] = make_float2(c, c);
    prev = pc;
    if (pc >= 1.f) { nb = k + 1; break; }
  }

  int jmin = t - nb + 1;                       // deepest j with nonzero coeff
  #pragma unroll
  for (int o = 1; o < TT; o <<= 1)
    jmin = min(jmin, __shfl_xor_sync(0xffffffffu, jmin, o));

  const float2 z = make_float2(0.f, 0.f);
  const int kpad = t - jmin;                   // need row[k] valid for k<=kpad
  for (int kk = nb; kk <= kpad; ++kk) row[kk] = z;

  if ((t & (TT - 1)) == 0) g_jmin[(t / TT) * B_DIM + b] = jmin;
}

// ---------------------------------------------------------------------------
// Kernel 3: tiled banded read. Block = (t-tile of 16, b), 64 threads x float4.
// Peel triangle j in (t0, t_hi] via uniform __ldg; main region [j_min, t0]
// staged through smem in 64-j chunks (exact window, no guards thanks to the
// walk kernel's padding). One v-row LDG.128 feeds 16 outputs via 32 FFMA2.
// ---------------------------------------------------------------------------
__global__ __launch_bounds__(64) void read_tile_kernel(
    const float* __restrict__ v, float* __restrict__ out) {
  const int t0  = blockIdx.x * TT;
  const int b   = blockIdx.y;
  const int tid = threadIdx.x;

  __shared__ float2 sc[TT][CH];                // 8 KB

  const int j_min = g_jmin[blockIdx.x * B_DIM + b];

  const ulonglong2* __restrict__ vb =
      (const ulonglong2*)(v + (size_t)b * E_DIM) + tid;  // 16B per thread
  const size_t row2 = (size_t)B_DIM * E_DIM / 4;         // row stride in 16B

  const float2* __restrict__ bcbase =
      &g_bc2[((size_t)t0 * B_DIM + b) * KMAX];
  const size_t tstride = (size_t)B_DIM * KMAX;           // row-to-row (float2)

  ull a0[TT], a1[TT];
  #pragma unroll
  for (int tl = 0; tl < TT; ++tl) { a0[tl] = 0ull; a1[tl] = 0ull; }

  // ---- peel: j = t0+1 .. t0+TT-1 (k = tl - jo, safe: padded rows) ----
  for (int jo = 1; jo < TT; ++jo) {
    const ulonglong2 vv = vb[(size_t)(t0 + jo) * row2];
    #pragma unroll
    for (int tl = 0; tl < TT; ++tl) {
      if (tl >= jo) {
        const ull cc = __ldg((const ull*)(bcbase + (size_t)tl * tstride +
                                          (tl - jo)));
        a0[tl] = ffma2(cc, vv.x, a0[tl]);
        a1[tl] = ffma2(cc, vv.y, a1[tl]);
      }
    }
  }

  // ---- main region [j_min, t0], staged in CH-sized chunks ----
  for (int jc = j_min; jc <= t0; jc += CH) {
    const int L = min(CH, t0 - jc + 1);
    __syncthreads();
    if (tid < L) {
      const int kbase = t0 - jc - tid;         // k for this jj, tl=0
      #pragma unroll
      for (int tl = 0; tl < TT; ++tl)
        sc[tl][tid] = __ldg(bcbase + (size_t)tl * tstride + (kbase + tl));
    }
    __syncthreads();

    for (int jj = 0; jj < L; ++jj) {
      const ulonglong2 vv = vb[(size_t)(jc + jj) * row2];
      #pragma unroll
      for (int tl = 0; tl < TT; ++tl) {
        const ull cc = *(const ull*)&sc[tl][jj];   // LDS.64 broadcast
        a0[tl] = ffma2(cc, vv.x, a0[tl]);
        a1[tl] = ffma2(cc, vv.y, a1[tl]);
      }
    }
  }

  #pragma unroll
  for (int tl = 0; tl < TT; ++tl) {
    ulonglong2 r; r.x = a0[tl]; r.y = a1[tl];
    ((ulonglong2*)out)[((size_t)(t0 + tl) * B_DIM + b) * (E_DIM / 4) + tid] = r;
  }
}

// ---------------------------------------------------------------------------
// Inputs: v [T,B,E] f32, u [T,B] f32, d [T,B] f32. Output: reads [T,B,E] f32.
// ---------------------------------------------------------------------------
extern "C" void kernel_launch(void* const* d_in, const int* in_sizes, int n_in,
                              void* d_out, int out_size) {
  const float* v = (const float*)d_in[0];
  const float* u = (const float*)d_in[1];
  const float* d = (const float*)d_in[2];
  float* out = (float*)d_out;

  prefix_kernel<<<B_DIM, T_DIM>>>(u, d);
  walk_kernel<<<B_DIM * 2, 256>>>();

  dim3 grid(T_DIM / TT, B_DIM);
  read_tile_kernel<<<grid, 64>>>(v, out);
}